// round 6
// baseline (speedup 1.0000x reference)
#include <cuda_runtime.h>
#include <cuda_fp16.h>
#include <stdint.h>

#define TT       365
#define BATCH    4096
#define NTHREADS 256
#define MTILE    32           // batch rows per CTA
#define NCTA     128
#define KSTEPS   18           // K=288/16
#define NTILES   128          // 1024/8
#define LDA      296          // A smem row stride (halfs)
#define GLD      1032         // gates smem row stride (floats)

#define SMEM_A_BYTES  (MTILE * LDA * 2)          // 18944
#define SMEM_G_BYTES  (MTILE * GLD * 4)          // 132096
#define SMEM_BYTES    (SMEM_A_BYTES + SMEM_G_BYTES)

// Pre-swizzled fp16 weights in mma.m16n8k16 B-fragment order.
// Index: ((ks*128 + ntile)*32 + lane) -> uint2 {B[k,n]B[k+1,n], B[k+8,n]B[k+9,n]}
__device__ uint2 g_WcSwz[KSTEPS * NTILES * 32];

// ---------------------------------------------------------------------------
__global__ void lstm_prep_kernel(const float* __restrict__ w_ih,
                                 const float* __restrict__ w_hh) {
    int g = blockIdx.x * blockDim.x + threadIdx.x;
    if (g >= KSTEPS * NTILES * 32) return;
    int lane  = g & 31;
    int ntile = (g >> 5) & 127;
    int kstep = g >> 12;
    int n0 = ntile * 8 + (lane >> 2);
    int kb = kstep * 16 + 2 * (lane & 3);

    float v[4];
    int koffs[4] = {kb, kb + 1, kb + 8, kb + 9};
#pragma unroll
    for (int u = 0; u < 4; u++) {
        int k = koffs[u];
        v[u] = (k < 256) ? w_hh[n0 * 256 + k] : w_ih[n0 * 32 + (k - 256)];
    }
    unsigned x = ((unsigned)__half_as_ushort(__float2half(v[1])) << 16)
               |  (unsigned)__half_as_ushort(__float2half(v[0]));
    unsigned y = ((unsigned)__half_as_ushort(__float2half(v[3])) << 16)
               |  (unsigned)__half_as_ushort(__float2half(v[2]));
    uint2 val; val.x = x; val.y = y;
    g_WcSwz[g] = val;
}

// ---------------------------------------------------------------------------
__device__ __forceinline__ unsigned smem_u32(const void* p) {
    return (unsigned)__cvta_generic_to_shared(p);
}
__device__ __forceinline__ void ldmatrix_x4(unsigned addr, unsigned& r0,
                                            unsigned& r1, unsigned& r2, unsigned& r3) {
    asm volatile("ldmatrix.sync.aligned.m8n8.x4.shared.b16 {%0,%1,%2,%3}, [%4];\n"
                 : "=r"(r0), "=r"(r1), "=r"(r2), "=r"(r3) : "r"(addr));
}
__device__ __forceinline__ void mma16816(float* c, unsigned a0, unsigned a1,
                                         unsigned a2, unsigned a3,
                                         unsigned b0, unsigned b1) {
    asm volatile(
        "mma.sync.aligned.m16n8k16.row.col.f32.f16.f16.f32 "
        "{%0,%1,%2,%3}, {%4,%5,%6,%7}, {%8,%9}, {%0,%1,%2,%3};\n"
        : "+f"(c[0]), "+f"(c[1]), "+f"(c[2]), "+f"(c[3])
        : "r"(a0), "r"(a1), "r"(a2), "r"(a3), "r"(b0), "r"(b1));
}

// 8-MUFU LSTM cell; thread owns hidden col j (gates layout [i|f|g|o] x 256)
__device__ __forceinline__ void cell_update(const float* gr, float& c,
                                            float bi, float bf, float bg, float bo,
                                            __half* adst) {
    float pi = gr[0]   + bi;
    float pf = gr[256] + bf;
    float pg = gr[512] + bg;
    float po = gr[768] + bo;
    float ei = __expf(-pi);
    float ef = __expf(-pf);
    float eo = __expf(-po);
    float eg = __expf(-2.f * fabsf(pg));
    float fg  = __fdividef(1.f, 1.f + ef);
    float itg = (1.f - eg) * __fdividef(1.f, (1.f + ei) * (1.f + eg));
    c = fg * c + copysignf(itg, pg);
    float ec = __expf(-2.f * fabsf(c));
    float hm = (1.f - ec) * __fdividef(1.f, (1.f + eo) * (1.f + ec));
    *adst = __float2half(copysignf(hm, c));
}

// One M-half GEMM (16 rows x 1024 cols), optionally interleaving 16 cell
// updates (rows CELLBASE..+15, disjoint from the GEMM's rows) into the k-loop.
template <int MH, bool DC>
__device__ __forceinline__ void gemm_half(__half* A_h, float* gates,
                                          int warp, int lane, int tid,
                                          int aRowOff, int aColOff,
                                          int cellbase, float* cc,
                                          float bi, float bf, float bg, float bo) {
    float acc[16][4];
#pragma unroll
    for (int nt = 0; nt < 16; nt++)
#pragma unroll
        for (int u = 0; u < 4; u++) acc[nt][u] = 0.f;

#pragma unroll
    for (int ks = 0; ks < KSTEPS; ks++) {
        unsigned a0, a1, a2, a3;
        const __half* p = A_h + (MH * 16 + aRowOff) * LDA + ks * 16 + aColOff;
        ldmatrix_x4(smem_u32(p), a0, a1, a2, a3);
        const uint2* wp = g_WcSwz + (ks * NTILES + warp * 16) * 32 + lane;
#pragma unroll
        for (int nt = 0; nt < 16; nt++) {
            uint2 bb = __ldcg(wp + nt * 32);
            mma16816(acc[nt], a0, a1, a2, a3, bb.x, bb.y);
        }
        if (DC && ks < 16) {
            int row = cellbase + ks;
            cell_update(gates + row * GLD + tid, cc[ks], bi, bf, bg, bo,
                        A_h + row * LDA + tid);
        }
    }
    // accumulators -> gates smem (rows MH*16 .. MH*16+15)
    const int cRow = lane >> 2;
    const int cCol = (lane & 3) * 2;
#pragma unroll
    for (int nt = 0; nt < 16; nt++) {
        int ncol = warp * 128 + nt * 8 + cCol;
        *(float2*)&gates[(MH * 16 + cRow) * GLD + ncol] =
            make_float2(acc[nt][0], acc[nt][1]);
        *(float2*)&gates[(MH * 16 + cRow + 8) * GLD + ncol] =
            make_float2(acc[nt][2], acc[nt][3]);
    }
}

// ---------------------------------------------------------------------------
// Persistent kernel: CTA owns 32 batch rows; 2-stage M-split pipeline hides
// all cell MUFU under the tensor phases.
__global__ void __launch_bounds__(NTHREADS, 1)
lstm_main_kernel(const float* __restrict__ xd,
                 const float* __restrict__ b,
                 const float* __restrict__ w_out,
                 const float* __restrict__ b_out,
                 float* __restrict__ out) {
    extern __shared__ char smem[];
    __half* A_h   = (__half*)smem;                   // [32][LDA] = [h(256)|x(32)]
    float*  gates = (float*)(smem + SMEM_A_BYTES);   // [32][GLD]

    const int tid  = threadIdx.x;
    const int lane = tid & 31;
    const int warp = tid >> 5;
    const int rowbase = blockIdx.x * MTILE;

    const float bi = b[tid];
    const float bf = b[tid + 256];
    const float bg = b[tid + 512];
    const float bo = b[tid + 768];

    // ldmatrix lane address components
    const int lrow = lane & 7;
    const int lsel = lane >> 3;
    const int aRowOff = lrow + ((lsel & 1) << 3);
    const int aColOff = (lsel >> 1) << 3;

    float c0[16], c1[16];
#pragma unroll
    for (int k = 0; k < 16; k++) { c0[k] = 0.f; c1[k] = 0.f; }

    // zero h-part of A
    for (int idx = tid; idx < MTILE * 128; idx += NTHREADS) {
        int r = idx >> 7, c2 = idx & 127;
        ((__half2*)(A_h + r * LDA))[c2] = __half2half2(__float2half(0.f));
    }

    for (int t = 0; t < TT; t++) {
        // ---- stage x_t into A[:, 256:288] (fp32 -> fp16) ----
#pragma unroll
        for (int u = 0; u < 2; u++) {
            int idx = tid + u * NTHREADS;            // 0..511 float2 units
            int row = idx >> 4, i2 = idx & 15;
            float2 v = __ldcs((const float2*)(xd + (rowbase + row) * (TT * 32) + t * 32) + i2);
            ((__half2*)(A_h + row * LDA + 256))[i2] = __floats2half2_rn(v.x, v.y);
        }
        __syncthreads();

        // ---- phase A: GEMM rows 0-15  ||  cells rows 16-31 of step t-1 ----
        if (t > 0)
            gemm_half<0, true >(A_h, gates, warp, lane, tid, aRowOff, aColOff,
                                16, c1, bi, bf, bg, bo);
        else
            gemm_half<0, false>(A_h, gates, warp, lane, tid, aRowOff, aColOff,
                                16, c1, bi, bf, bg, bo);
        __syncthreads();

        // ---- phase B: GEMM rows 16-31 ||  cells rows 0-15 of step t ----
        gemm_half<1, true>(A_h, gates, warp, lane, tid, aRowOff, aColOff,
                           0, c0, bi, bf, bg, bo);
        __syncthreads();
    }

    // ---- tail: cells rows 16-31 of final step ----
#pragma unroll
    for (int k = 0; k < 16; k++) {
        int row = 16 + k;
        cell_update(gates + row * GLD + tid, c1[k], bi, bf, bg, bo,
                    A_h + row * LDA + tid);
    }
    __syncthreads();

    // ---- output: out[row] = relu(h_T . w_out + b_out) ----
    float wj = w_out[tid];
#pragma unroll
    for (int k = 0; k < MTILE; k++)
        gates[k * GLD + tid] = __half2float(A_h[k * LDA + tid]) * wj;
    __syncthreads();

    float bo0 = b_out[0];
#pragma unroll
    for (int rr = 0; rr < 4; rr++) {
        int k = warp * 4 + rr;
        float s = 0.f;
#pragma unroll
        for (int u = 0; u < 8; u++) s += gates[k * GLD + lane + u * 32];
#pragma unroll
        for (int off = 16; off; off >>= 1) s += __shfl_xor_sync(0xffffffffu, s, off);
        if (lane == 0) out[rowbase + k] = fmaxf(s + bo0, 0.f);
    }
}

// ---------------------------------------------------------------------------
extern "C" void kernel_launch(void* const* d_in, const int* in_sizes, int n_in,
                              void* d_out, int out_size) {
    const float* xd    = (const float*)d_in[0];
    const float* w_ih  = (const float*)d_in[1];
    const float* w_hh  = (const float*)d_in[2];
    const float* b     = (const float*)d_in[3];
    const float* w_out = (const float*)d_in[4];
    const float* b_out = (const float*)d_in[5];
    float* out = (float*)d_out;

    cudaFuncSetAttribute(lstm_main_kernel,
                         cudaFuncAttributeMaxDynamicSharedMemorySize, SMEM_BYTES);

    lstm_prep_kernel<<<288, 256>>>(w_ih, w_hh);
    lstm_main_kernel<<<NCTA, NTHREADS, SMEM_BYTES>>>(xd, b, w_out, b_out, out);
}

// round 7
// speedup vs baseline: 1.1254x; 1.1254x over previous
#include <cuda_runtime.h>
#include <cuda_fp16.h>
#include <stdint.h>

#define TT       365
#define BATCH    4096
#define NTHREADS 512          // 16 warps
#define MTILE    32           // batch rows per CTA
#define NCTA     128
#define KSTEPS   18           // K=288/16
#define NTILES   128          // 1024/8
#define LDA      296          // A smem row stride (halfs)
#define GLD      1032         // gates smem row stride (floats)

#define SMEM_A_BYTES  (MTILE * LDA * 2)          // 18944
#define SMEM_G_BYTES  (MTILE * GLD * 4)          // 132096
#define SMEM_BYTES    (SMEM_A_BYTES + SMEM_G_BYTES)

// Pre-swizzled fp16 weights in mma.m16n8k16 B-fragment order.
// Index: ((ks*128 + ntile)*32 + lane) -> uint2 {B[k,n]B[k+1,n], B[k+8,n]B[k+9,n]}
__device__ uint2 g_WcSwz[KSTEPS * NTILES * 32];

// ---------------------------------------------------------------------------
__global__ void lstm_prep_kernel(const float* __restrict__ w_ih,
                                 const float* __restrict__ w_hh) {
    int g = blockIdx.x * blockDim.x + threadIdx.x;
    if (g >= KSTEPS * NTILES * 32) return;
    int lane  = g & 31;
    int ntile = (g >> 5) & 127;
    int kstep = g >> 12;
    int n0 = ntile * 8 + (lane >> 2);
    int kb = kstep * 16 + 2 * (lane & 3);

    float v[4];
    int koffs[4] = {kb, kb + 1, kb + 8, kb + 9};
#pragma unroll
    for (int u = 0; u < 4; u++) {
        int k = koffs[u];
        v[u] = (k < 256) ? w_hh[n0 * 256 + k] : w_ih[n0 * 32 + (k - 256)];
    }
    unsigned x = ((unsigned)__half_as_ushort(__float2half(v[1])) << 16)
               |  (unsigned)__half_as_ushort(__float2half(v[0]));
    unsigned y = ((unsigned)__half_as_ushort(__float2half(v[3])) << 16)
               |  (unsigned)__half_as_ushort(__float2half(v[2]));
    uint2 val; val.x = x; val.y = y;
    g_WcSwz[g] = val;
}

// ---------------------------------------------------------------------------
__device__ __forceinline__ unsigned smem_u32(const void* p) {
    return (unsigned)__cvta_generic_to_shared(p);
}
__device__ __forceinline__ void ldmatrix_x4(unsigned addr, unsigned& r0,
                                            unsigned& r1, unsigned& r2, unsigned& r3) {
    asm volatile("ldmatrix.sync.aligned.m8n8.x4.shared.b16 {%0,%1,%2,%3}, [%4];\n"
                 : "=r"(r0), "=r"(r1), "=r"(r2), "=r"(r3) : "r"(addr));
}
__device__ __forceinline__ void mma16816(float* c, unsigned a0, unsigned a1,
                                         unsigned a2, unsigned a3,
                                         unsigned b0, unsigned b1) {
    asm volatile(
        "mma.sync.aligned.m16n8k16.row.col.f32.f16.f16.f32 "
        "{%0,%1,%2,%3}, {%4,%5,%6,%7}, {%8,%9}, {%0,%1,%2,%3};\n"
        : "+f"(c[0]), "+f"(c[1]), "+f"(c[2]), "+f"(c[3])
        : "r"(a0), "r"(a1), "r"(a2), "r"(a3), "r"(b0), "r"(b1));
}

// 8-MUFU LSTM cell; thread owns hidden col j (gates layout [i|f|g|o] x 256)
__device__ __forceinline__ void cell_update(const float* gr, float& c,
                                            float bi, float bf, float bg, float bo,
                                            __half* adst) {
    float pi = gr[0]   + bi;
    float pf = gr[256] + bf;
    float pg = gr[512] + bg;
    float po = gr[768] + bo;
    float ei = __expf(-pi);
    float ef = __expf(-pf);
    float eo = __expf(-po);
    float eg = __expf(-2.f * fabsf(pg));
    float fg  = __fdividef(1.f, 1.f + ef);
    float itg = (1.f - eg) * __fdividef(1.f, (1.f + ei) * (1.f + eg));
    c = fg * c + copysignf(itg, pg);
    float ec = __expf(-2.f * fabsf(c));
    float hm = (1.f - ec) * __fdividef(1.f, (1.f + eo) * (1.f + ec));
    *adst = __float2half(copysignf(hm, c));
}

// ---------------------------------------------------------------------------
// Persistent kernel: CTA owns 32 batch rows. 16 warps; warp w computes the
// full M=32 over its 64 gate columns (8 ntiles). 2 syncs per step.
__global__ void __launch_bounds__(NTHREADS, 1)
lstm_main_kernel(const float* __restrict__ xd,
                 const float* __restrict__ b,
                 const float* __restrict__ w_out,
                 const float* __restrict__ b_out,
                 float* __restrict__ out) {
    extern __shared__ char smem[];
    __half* A_h   = (__half*)smem;                   // [32][LDA] = [h(256)|x(32)]
    float*  gates = (float*)(smem + SMEM_A_BYTES);   // [32][GLD]

    const int tid  = threadIdx.x;
    const int lane = tid & 31;
    const int warp = tid >> 5;                       // 0..15
    const int rowbase = blockIdx.x * MTILE;

    // cell ownership: col j, row half rh (16 rows each)
    const int jj = tid & 255;
    const int rh = tid >> 8;                         // 0 or 1

    const float bi = b[jj];
    const float bf = b[jj + 256];
    const float bg = b[jj + 512];
    const float bo = b[jj + 768];

    // ldmatrix lane address components
    const int lrow = lane & 7;
    const int lsel = lane >> 3;
    const int aRowOff = lrow + ((lsel & 1) << 3);
    const int aColOff = (lsel >> 1) << 3;

    // accumulator writeback coords
    const int cRow = lane >> 2;
    const int cCol = (lane & 3) * 2;

    float c_reg[16];
#pragma unroll
    for (int k = 0; k < 16; k++) c_reg[k] = 0.f;

    // zero h-part of A
    for (int idx = tid; idx < MTILE * 128; idx += NTHREADS) {
        int r = idx >> 7, c2 = idx & 127;
        ((__half2*)(A_h + r * LDA))[c2] = __half2half2(__float2half(0.f));
    }

    // stage x_0 (one pass: 512 threads == 512 float2 elements = 32 rows x 16)
    {
        int row = tid >> 4, i2 = tid & 15;
        float2 v = __ldcs((const float2*)(xd + (rowbase + row) * (TT * 32)) + i2);
        ((__half2*)(A_h + row * LDA + 256))[i2] = __floats2half2_rn(v.x, v.y);
    }
    __syncthreads();

    for (int t = 0; t < TT; t++) {
        // ---- GEMM: gates[32x1024] = [h|x] @ Wc^T; warp covers 64 N-cols ----
        float acc[2][8][4];
#pragma unroll
        for (int mt = 0; mt < 2; mt++)
#pragma unroll
            for (int nt = 0; nt < 8; nt++)
#pragma unroll
                for (int u = 0; u < 4; u++) acc[mt][nt][u] = 0.f;

#pragma unroll
        for (int ks = 0; ks < KSTEPS; ks++) {
            unsigned a[2][4];
#pragma unroll
            for (int mt = 0; mt < 2; mt++) {
                const __half* p = A_h + (mt * 16 + aRowOff) * LDA + ks * 16 + aColOff;
                ldmatrix_x4(smem_u32(p), a[mt][0], a[mt][1], a[mt][2], a[mt][3]);
            }
            const uint2* wp = g_WcSwz + (ks * NTILES + warp * 8) * 32 + lane;
#pragma unroll
            for (int nt = 0; nt < 8; nt++) {
                uint2 bb = __ldcg(wp + nt * 32);
                mma16816(acc[0][nt], a[0][0], a[0][1], a[0][2], a[0][3], bb.x, bb.y);
                mma16816(acc[1][nt], a[1][0], a[1][1], a[1][2], a[1][3], bb.x, bb.y);
            }
        }

        // accumulators -> gates smem (warp cols warp*64 .. +63)
#pragma unroll
        for (int mt = 0; mt < 2; mt++) {
#pragma unroll
            for (int nt = 0; nt < 8; nt++) {
                int ncol = warp * 64 + nt * 8 + cCol;
                *(float2*)&gates[(mt * 16 + cRow) * GLD + ncol] =
                    make_float2(acc[mt][nt][0], acc[mt][nt][1]);
                *(float2*)&gates[(mt * 16 + cRow + 8) * GLD + ncol] =
                    make_float2(acc[mt][nt][2], acc[mt][nt][3]);
            }
        }
        __syncthreads();

        // ---- cells (thread: col jj, rows rh*16..+15) + stage x_{t+1} ----
#pragma unroll
        for (int k = 0; k < 16; k++) {
            int row = rh * 16 + k;
            cell_update(gates + row * GLD + jj, c_reg[k], bi, bf, bg, bo,
                        A_h + row * LDA + jj);
        }
        if (t + 1 < TT) {
            int row = tid >> 4, i2 = tid & 15;
            float2 v = __ldcs((const float2*)(xd + (rowbase + row) * (TT * 32)
                                              + (t + 1) * 32) + i2);
            ((__half2*)(A_h + row * LDA + 256))[i2] = __floats2half2_rn(v.x, v.y);
        }
        __syncthreads();
    }

    // ---- output: out[row] = relu(h_T . w_out + b_out) ----
    {
        float wj = w_out[jj];
#pragma unroll
        for (int k = 0; k < 16; k++) {
            int row = rh * 16 + k;
            gates[row * GLD + jj] = __half2float(A_h[row * LDA + jj]) * wj;
        }
    }
    __syncthreads();

    if (tid < 256) {
        float bo0 = b_out[0];
#pragma unroll
        for (int rr = 0; rr < 4; rr++) {
            int k = (tid >> 5) * 4 + rr;             // warp 0..7 handle 4 rows each
            float s = 0.f;
#pragma unroll
            for (int u = 0; u < 8; u++) s += gates[k * GLD + lane + u * 32];
#pragma unroll
            for (int off = 16; off; off >>= 1) s += __shfl_xor_sync(0xffffffffu, s, off);
            if (lane == 0) out[rowbase + k] = fmaxf(s + bo0, 0.f);
        }
    }
}

// ---------------------------------------------------------------------------
extern "C" void kernel_launch(void* const* d_in, const int* in_sizes, int n_in,
                              void* d_out, int out_size) {
    const float* xd    = (const float*)d_in[0];
    const float* w_ih  = (const float*)d_in[1];
    const float* w_hh  = (const float*)d_in[2];
    const float* b     = (const float*)d_in[3];
    const float* w_out = (const float*)d_in[4];
    const float* b_out = (const float*)d_in[5];
    float* out = (float*)d_out;

    cudaFuncSetAttribute(lstm_main_kernel,
                         cudaFuncAttributeMaxDynamicSharedMemorySize, SMEM_BYTES);

    lstm_prep_kernel<<<288, 256>>>(w_ih, w_hh);
    lstm_main_kernel<<<NCTA, NTHREADS, SMEM_BYTES>>>(xd, b, w_out, b_out, out);
}

// round 8
// speedup vs baseline: 1.7964x; 1.5963x over previous
#include <cuda_runtime.h>
#include <cuda_fp16.h>
#include <stdint.h>

#define TT       365
#define BATCH    4096
#define NTHREADS 512          // 16 warps
#define MTILE    32           // batch rows per CTA
#define NCTA     128
#define KSTEPS   18           // K=288/16
#define NTILES   128          // 1024/8
#define LDA      296          // A smem row stride (halfs)
#define GLD      1032         // gates smem row stride (floats)

#define SMEM_A_BYTES  (MTILE * LDA * 2)          // 18944
#define SMEM_G_BYTES  (MTILE * GLD * 4)          // 132096
#define SMEM_BYTES    (SMEM_A_BYTES + SMEM_G_BYTES)

// Pre-swizzled fp16 weights in mma.m16n8k16 B-fragment order.
// Index: ((ks*128 + ntile)*32 + lane) -> uint2 {B[k,n]B[k+1,n], B[k+8,n]B[k+9,n]}
__device__ uint2 g_WcSwz[KSTEPS * NTILES * 32];

// ---------------------------------------------------------------------------
__global__ void lstm_prep_kernel(const float* __restrict__ w_ih,
                                 const float* __restrict__ w_hh) {
    int g = blockIdx.x * blockDim.x + threadIdx.x;
    if (g >= KSTEPS * NTILES * 32) return;
    int lane  = g & 31;
    int ntile = (g >> 5) & 127;
    int kstep = g >> 12;
    int n0 = ntile * 8 + (lane >> 2);
    int kb = kstep * 16 + 2 * (lane & 3);

    float v[4];
    int koffs[4] = {kb, kb + 1, kb + 8, kb + 9};
#pragma unroll
    for (int u = 0; u < 4; u++) {
        int k = koffs[u];
        v[u] = (k < 256) ? w_hh[n0 * 256 + k] : w_ih[n0 * 32 + (k - 256)];
    }
    unsigned x = ((unsigned)__half_as_ushort(__float2half(v[1])) << 16)
               |  (unsigned)__half_as_ushort(__float2half(v[0]));
    unsigned y = ((unsigned)__half_as_ushort(__float2half(v[3])) << 16)
               |  (unsigned)__half_as_ushort(__float2half(v[2]));
    uint2 val; val.x = x; val.y = y;
    g_WcSwz[g] = val;
}

// ---------------------------------------------------------------------------
__device__ __forceinline__ unsigned smem_u32(const void* p) {
    return (unsigned)__cvta_generic_to_shared(p);
}
__device__ __forceinline__ void ldmatrix_x4(unsigned addr, unsigned& r0,
                                            unsigned& r1, unsigned& r2, unsigned& r3) {
    asm volatile("ldmatrix.sync.aligned.m8n8.x4.shared.b16 {%0,%1,%2,%3}, [%4];\n"
                 : "=r"(r0), "=r"(r1), "=r"(r2), "=r"(r3) : "r"(addr));
}
__device__ __forceinline__ void mma16816(float* c, unsigned a0, unsigned a1,
                                         unsigned a2, unsigned a3,
                                         unsigned b0, unsigned b1) {
    asm volatile(
        "mma.sync.aligned.m16n8k16.row.col.f32.f16.f16.f32 "
        "{%0,%1,%2,%3}, {%4,%5,%6,%7}, {%8,%9}, {%0,%1,%2,%3};\n"
        : "+f"(c[0]), "+f"(c[1]), "+f"(c[2]), "+f"(c[3])
        : "r"(a0), "r"(a1), "r"(a2), "r"(a3), "r"(b0), "r"(b1));
}

// 8-MUFU LSTM cell; thread owns hidden col j (gates layout [i|f|g|o] x 256)
__device__ __forceinline__ void cell_update(const float* gr, float& c,
                                            float bi, float bf, float bg, float bo,
                                            __half* adst) {
    float pi = gr[0]   + bi;
    float pf = gr[256] + bf;
    float pg = gr[512] + bg;
    float po = gr[768] + bo;
    float ei = __expf(-pi);
    float ef = __expf(-pf);
    float eo = __expf(-po);
    float eg = __expf(-2.f * fabsf(pg));
    float fg  = __fdividef(1.f, 1.f + ef);
    float itg = (1.f - eg) * __fdividef(1.f, (1.f + ei) * (1.f + eg));
    c = fg * c + copysignf(itg, pg);
    float ec = __expf(-2.f * fabsf(c));
    float hm = (1.f - ec) * __fdividef(1.f, (1.f + eo) * (1.f + ec));
    *adst = __float2half(copysignf(hm, c));
}

// ---------------------------------------------------------------------------
// Persistent kernel: CTA owns 32 batch rows. 16 warps; warp w computes the
// full M=32 over its 64 gate columns (8 ntiles). 2 syncs per step.
__global__ void __launch_bounds__(NTHREADS, 1)
lstm_main_kernel(const float* __restrict__ xd,
                 const float* __restrict__ b,
                 const float* __restrict__ w_out,
                 const float* __restrict__ b_out,
                 float* __restrict__ out) {
    extern __shared__ char smem[];
    __half* A_h   = (__half*)smem;                   // [32][LDA] = [h(256)|x(32)]
    float*  gates = (float*)(smem + SMEM_A_BYTES);   // [32][GLD]

    const int tid  = threadIdx.x;
    const int lane = tid & 31;
    const int warp = tid >> 5;                       // 0..15
    const int rowbase = blockIdx.x * MTILE;

    // cell ownership: col j, row half rh (16 rows each)
    const int jj = tid & 255;
    const int rh = tid >> 8;                         // 0 or 1

    const float bi = b[jj];
    const float bf = b[jj + 256];
    const float bg = b[jj + 512];
    const float bo = b[jj + 768];

    // ldmatrix lane address components
    const int lrow = lane & 7;
    const int lsel = lane >> 3;
    const int aRowOff = lrow + ((lsel & 1) << 3);
    const int aColOff = (lsel >> 1) << 3;

    // accumulator writeback coords
    const int cRow = lane >> 2;
    const int cCol = (lane & 3) * 2;

    float c_reg[16];
#pragma unroll
    for (int k = 0; k < 16; k++) c_reg[k] = 0.f;

    // zero h-part of A
    for (int idx = tid; idx < MTILE * 128; idx += NTHREADS) {
        int r = idx >> 7, c2 = idx & 127;
        ((__half2*)(A_h + r * LDA))[c2] = __half2half2(__float2half(0.f));
    }

    // stage x_0 (one pass: 512 threads == 512 float2 elements = 32 rows x 16)
    {
        int row = tid >> 4, i2 = tid & 15;
        float2 v = __ldcs((const float2*)(xd + (rowbase + row) * (TT * 32)) + i2);
        ((__half2*)(A_h + row * LDA + 256))[i2] = __floats2half2_rn(v.x, v.y);
    }
    __syncthreads();

    for (int t = 0; t < TT; t++) {
        // ---- GEMM: gates[32x1024] = [h|x] @ Wc^T; warp covers 64 N-cols ----
        float acc[2][8][4];
#pragma unroll
        for (int mt = 0; mt < 2; mt++)
#pragma unroll
            for (int nt = 0; nt < 8; nt++)
#pragma unroll
                for (int u = 0; u < 4; u++) acc[mt][nt][u] = 0.f;

#pragma unroll
        for (int ks = 0; ks < KSTEPS; ks++) {
            unsigned a[2][4];
#pragma unroll
            for (int mt = 0; mt < 2; mt++) {
                const __half* p = A_h + (mt * 16 + aRowOff) * LDA + ks * 16 + aColOff;
                ldmatrix_x4(smem_u32(p), a[mt][0], a[mt][1], a[mt][2], a[mt][3]);
            }
            const uint2* wp = g_WcSwz + (ks * NTILES + warp * 8) * 32 + lane;
#pragma unroll
            for (int nt = 0; nt < 8; nt++) {
                uint2 bb = __ldcg(wp + nt * 32);
                mma16816(acc[0][nt], a[0][0], a[0][1], a[0][2], a[0][3], bb.x, bb.y);
                mma16816(acc[1][nt], a[1][0], a[1][1], a[1][2], a[1][3], bb.x, bb.y);
            }
        }

        // accumulators -> gates smem (warp cols warp*64 .. +63)
#pragma unroll
        for (int mt = 0; mt < 2; mt++) {
#pragma unroll
            for (int nt = 0; nt < 8; nt++) {
                int ncol = warp * 64 + nt * 8 + cCol;
                *(float2*)&gates[(mt * 16 + cRow) * GLD + ncol] =
                    make_float2(acc[mt][nt][0], acc[mt][nt][1]);
                *(float2*)&gates[(mt * 16 + cRow + 8) * GLD + ncol] =
                    make_float2(acc[mt][nt][2], acc[mt][nt][3]);
            }
        }
        __syncthreads();

        // ---- cells (thread: col jj, rows rh*16..+15) + stage x_{t+1} ----
#pragma unroll
        for (int k = 0; k < 16; k++) {
            int row = rh * 16 + k;
            cell_update(gates + row * GLD + jj, c_reg[k], bi, bf, bg, bo,
                        A_h + row * LDA + jj);
        }
        if (t + 1 < TT) {
            int row = tid >> 4, i2 = tid & 15;
            float2 v = __ldcs((const float2*)(xd + (rowbase + row) * (TT * 32)
                                              + (t + 1) * 32) + i2);
            ((__half2*)(A_h + row * LDA + 256))[i2] = __floats2half2_rn(v.x, v.y);
        }
        __syncthreads();
    }

    // ---- output: out[row] = relu(h_T . w_out + b_out) ----
    {
        float wj = w_out[jj];
#pragma unroll
        for (int k = 0; k < 16; k++) {
            int row = rh * 16 + k;
            gates[row * GLD + jj] = __half2float(A_h[row * LDA + jj]) * wj;
        }
    }
    __syncthreads();

    if (tid < 256) {
        float bo0 = b_out[0];
#pragma unroll
        for (int rr = 0; rr < 4; rr++) {
            int k = (tid >> 5) * 4 + rr;             // warp 0..7 handle 4 rows each
            float s = 0.f;
#pragma unroll
            for (int u = 0; u < 8; u++) s += gates[k * GLD + lane + u * 32];
#pragma unroll
            for (int off = 16; off; off >>= 1) s += __shfl_xor_sync(0xffffffffu, s, off);
            if (lane == 0) out[rowbase + k] = fmaxf(s + bo0, 0.f);
        }
    }
}

// ---------------------------------------------------------------------------
extern "C" void kernel_launch(void* const* d_in, const int* in_sizes, int n_in,
                              void* d_out, int out_size) {
    const float* xd    = (const float*)d_in[0];
    const float* w_ih  = (const float*)d_in[1];
    const float* w_hh  = (const float*)d_in[2];
    const float* b     = (const float*)d_in[3];
    const float* w_out = (const float*)d_in[4];
    const float* b_out = (const float*)d_in[5];
    float* out = (float*)d_out;

    cudaFuncSetAttribute(lstm_main_kernel,
                         cudaFuncAttributeMaxDynamicSharedMemorySize, SMEM_BYTES);

    lstm_prep_kernel<<<288, 256>>>(w_ih, w_hh);
    lstm_main_kernel<<<NCTA, NTHREADS, SMEM_BYTES>>>(xd, b, w_out, b_out, out);
}